// round 6
// baseline (speedup 1.0000x reference)
#include <cuda_runtime.h>

#define D      64
#define NSEG   8192
#define SEGS   16   // segments per block in kernel 2

// Scratch: per-segment maxes for both types. 2*8192*64*4 = 4 MB.
__device__ float g_segmax[2 * NSEG * D];

__device__ __forceinline__ void fmax4(float4& a, const float4 b) {
    a.x = fmaxf(a.x, b.x); a.y = fmaxf(a.y, b.y);
    a.z = fmaxf(a.z, b.z); a.w = fmaxf(a.w, b.w);
}

// ---------------------------------------------------------------------------
// Kernel 1 (UNCHANGED — measured at the DRAM wall, 6.6 TB/s):
// per-segment max over contiguous row ranges, one 256-thread block/segment,
// 16 float4-cols x 16 row-groups, MLP=4 with __ldcs streaming loads.
// ptr arrays are int32 (JAX x64 disabled downcasts the int64 ptr).
// ---------------------------------------------------------------------------
__global__ void __launch_bounds__(256)
seg_max_kernel(const float* __restrict__ x_a,
               const float* __restrict__ x_b,
               const int* __restrict__ ptr_a,
               const int* __restrict__ ptr_b,
               float* __restrict__ out)
{
    const int bid  = blockIdx.x;               // [0, 2*NSEG)
    const int type = (bid >= NSEG) ? 1 : 0;
    const int g    = type ? (bid - NSEG) : bid;

    const float* x   = type ? x_b   : x_a;
    const int*   ptr = type ? ptr_b : ptr_a;

    const int s = ptr[g];
    const int e = ptr[g + 1];

    const int tid = threadIdx.x;               // 256
    const int c4  = tid & 15;                  // float4 column 0..15
    const int rg  = tid >> 4;                  // row group 0..15

    const float NEG = -3.402823466e38f;
    float4 m0 = make_float4(NEG, NEG, NEG, NEG);
    float4 m1 = m0, m2 = m0, m3 = m0;

    const float4* __restrict__ xv = reinterpret_cast<const float4*>(x);

    long long row = (long long)s + rg;
    for (; row + 48 < e; row += 64) {
        const float4* p = xv + row * (D / 4) + c4;
        float4 v0 = __ldcs(p);
        float4 v1 = __ldcs(p + 16 * (D / 4));
        float4 v2 = __ldcs(p + 32 * (D / 4));
        float4 v3 = __ldcs(p + 48 * (D / 4));
        fmax4(m0, v0); fmax4(m1, v1); fmax4(m2, v2); fmax4(m3, v3);
    }
    for (; row < e; row += 16) {
        float4 v0 = __ldcs(xv + row * (D / 4) + c4);
        fmax4(m0, v0);
    }
    fmax4(m0, m1); fmax4(m2, m3); fmax4(m0, m2);

    __shared__ float4 sm[16][16];
    sm[rg][c4] = m0;
    __syncthreads();

    if (tid < 16) {
        float4 m = sm[0][tid];
        #pragma unroll
        for (int j = 1; j < 16; j++)
            fmax4(m, sm[j][tid]);
        float4* dst = reinterpret_cast<float4*>(
            &g_segmax[(size_t)(type * NSEG + g) * D]);
        dst[tid] = m;
    }

    // Initialize output to 0 (== relu floor); ordered before kernel 2 by stream.
    if (bid == 0 && tid < 128) out[tid] = 0.0f;
}

// ---------------------------------------------------------------------------
// Kernel 2: per-segment 64->128 linear + relu + global max. Split-K version:
// 256 threads = 128 outputs x 2 K-halves. Thread (o,h) holds W[o, h*32:h*32+32]
// in registers (8 float4), accumulates per-segment half-dots with 8 independent
// FMA chains (2 segs x 4 partials), writes partials to shared; a final
// 128-thread pass combines halves + bias + max + atomicMax.
// relu(max_g h) == max_g max(0, h); int-bit atomicMax is exact ordering for
// non-negative IEEE floats.
// ---------------------------------------------------------------------------
__global__ void __launch_bounds__(256)
gemm_max_kernel(const float* __restrict__ W_a,
                const float* __restrict__ W_b,
                const float* __restrict__ b_a,
                const float* __restrict__ b_b,
                float* __restrict__ out)
{
    const int blocks_per_type = NSEG / SEGS;          // 512
    const int bid   = blockIdx.x;                     // [0, 1024)
    const int type  = (bid >= blocks_per_type) ? 1 : 0;
    const int gbase = (type ? (bid - blocks_per_type) : bid) * SEGS;

    const float* __restrict__ W    = type ? W_b : W_a;
    const float* __restrict__ bias = type ? b_b : b_a;

    const int tid = threadIdx.x;                      // 0..255
    const int o   = tid & 127;                        // output channel
    const int h   = tid >> 7;                         // K-half 0/1

    // Half of W row o in registers: k in [h*32, h*32+32)
    float4 w[8];
    {
        const float4* W4 = reinterpret_cast<const float4*>(W + o * D + h * 32);
        #pragma unroll
        for (int k = 0; k < 8; k++) w[k] = W4[k];
    }

    __shared__ float4 sm[SEGS][D / 4];                // 4 KB
    {
        const float4* src = reinterpret_cast<const float4*>(
            &g_segmax[(size_t)(type * NSEG + gbase) * D]);
        sm[tid / (D / 4)][tid % (D / 4)] = src[tid];  // 256 float4 == 256 thr
    }
    __syncthreads();

    __shared__ float sp[2][128][SEGS];                // 16 KB partial half-dots

    #pragma unroll
    for (int s = 0; s < SEGS; s += 2) {
        float a0 = 0.f, a1 = 0.f, a2 = 0.f, a3 = 0.f;   // seg s
        float c0 = 0.f, c1 = 0.f, c2 = 0.f, c3 = 0.f;   // seg s+1
        #pragma unroll
        for (int k = 0; k < 8; k++) {
            float4 u  = sm[s][h * 8 + k];
            float4 v  = sm[s + 1][h * 8 + k];
            float4 ww = w[k];
            a0 = fmaf(ww.x, u.x, a0);
            a1 = fmaf(ww.y, u.y, a1);
            a2 = fmaf(ww.z, u.z, a2);
            a3 = fmaf(ww.w, u.w, a3);
            c0 = fmaf(ww.x, v.x, c0);
            c1 = fmaf(ww.y, v.y, c1);
            c2 = fmaf(ww.z, v.z, c2);
            c3 = fmaf(ww.w, v.w, c3);
        }
        sp[h][o][s]     = (a0 + a1) + (a2 + a3);
        sp[h][o][s + 1] = (c0 + c1) + (c2 + c3);
    }
    __syncthreads();

    if (tid < 128) {
        const float bo = bias[o];
        float lmax = 0.0f;  // relu floor
        #pragma unroll
        for (int s = 0; s < SEGS; s++) {
            float v = bo + sp[0][o][s] + sp[1][o][s];
            lmax = fmaxf(lmax, v);
        }
        atomicMax(reinterpret_cast<int*>(out) + o, __float_as_int(lmax));
    }
}

// ---------------------------------------------------------------------------
extern "C" void kernel_launch(void* const* d_in, const int* in_sizes, int n_in,
                              void* d_out, int out_size)
{
    const float* x_a   = (const float*)d_in[0];
    const float* x_b   = (const float*)d_in[1];
    const float* W_a   = (const float*)d_in[2];
    const float* W_b   = (const float*)d_in[3];
    const float* b_a   = (const float*)d_in[4];
    const float* b_b   = (const float*)d_in[5];
    const int*   ptr_a = (const int*)d_in[6];
    const int*   ptr_b = (const int*)d_in[7];
    float* out = (float*)d_out;

    seg_max_kernel<<<2 * NSEG, 256>>>(x_a, x_b, ptr_a, ptr_b, out);
    gemm_max_kernel<<<2 * (NSEG / SEGS), 256>>>(W_a, W_b, b_a, b_b, out);
}